// round 1
// baseline (speedup 1.0000x reference)
#include <cuda_runtime.h>
#include <math.h>

#define B 4
#define C 128
#define N 4096
#define TPB 256

// Scratch (device globals — no allocation allowed in kernel_launch)
__device__ float g_q[B*C*N];      // (b, c, n)
__device__ float g_k[B*C*N];      // (b, c, n)
__device__ float g_v[B*N*C];      // (b, n, c)  token-major for conflict-free attn tiles
__device__ float g_a[B*C*N];      // attention output, (b, c, n)
__device__ float g_wt[4*C*C];     // transposed weights: [which][c][o]

// ---------------------------------------------------------------------------
// Kernel 0: transpose weights to [c][o]
// ---------------------------------------------------------------------------
__global__ void wt_kernel(const float* __restrict__ Wq, const float* __restrict__ Wk,
                          const float* __restrict__ Wv, const float* __restrict__ Wo) {
    int w = blockIdx.x;
    const float* src = (w == 0) ? Wq : (w == 1) ? Wk : (w == 2) ? Wv : Wo;
    for (int idx = threadIdx.x; idx < C*C; idx += blockDim.x) {
        int o = idx >> 7, c = idx & 127;
        g_wt[w*C*C + c*C + o] = src[idx];
    }
}

// ---------------------------------------------------------------------------
// Kernel 1: QKV 1x1 conv.  out[o][i] = sum_c Wt[c][o] * x[c][i] + bias[o]
// grid (64 spatial tiles, 3 qkv, B), 256 threads, tile = 128 o x 64 i
// ---------------------------------------------------------------------------
__global__ __launch_bounds__(TPB) void qkv_kernel(const float* __restrict__ x,
        const float* __restrict__ bq, const float* __restrict__ bk,
        const float* __restrict__ bv) {
    extern __shared__ float sm[];
    float* Wt = sm;          // C*C   = 16384 floats
    float* Xs = sm + C*C;    // C*64  = 8192 floats
    int mode = blockIdx.y, b = blockIdx.z, i0 = blockIdx.x * 64;
    int tid = threadIdx.x;

    const float4* wsrc = (const float4*)(g_wt + mode*C*C);
#pragma unroll
    for (int r = 0; r < 16; r++) ((float4*)Wt)[tid + TPB*r] = wsrc[tid + TPB*r];
#pragma unroll
    for (int r = 0; r < 8; r++) {
        int idx4 = tid + TPB*r;
        int c = idx4 >> 4, j4 = idx4 & 15;
        ((float4*)Xs)[idx4] = *(const float4*)(x + (size_t)(b*C + c)*N + i0 + j4*4);
    }
    __syncthreads();

    int tx = tid & 15, ty = tid >> 4;           // tx -> i (4 each), ty -> o (8 each)
    const float* bias = (mode == 0) ? bq : (mode == 1) ? bk : bv;
    float acc[8][4];
#pragma unroll
    for (int oo = 0; oo < 8; oo++) {
        float bb = bias[ty*8 + oo];
#pragma unroll
        for (int ii = 0; ii < 4; ii++) acc[oo][ii] = bb;
    }

#pragma unroll 8
    for (int c = 0; c < C; c++) {
        float4 wa = *(float4*)&Wt[c*C + ty*8];
        float4 wb = *(float4*)&Wt[c*C + ty*8 + 4];
        float4 xv = *(float4*)&Xs[c*64 + tx*4];
        float w[8] = {wa.x, wa.y, wa.z, wa.w, wb.x, wb.y, wb.z, wb.w};
        float xr[4] = {xv.x, xv.y, xv.z, xv.w};
#pragma unroll
        for (int oo = 0; oo < 8; oo++)
#pragma unroll
            for (int ii = 0; ii < 4; ii++) acc[oo][ii] += w[oo] * xr[ii];
    }

    if (mode < 2) {
        float* dst = (mode == 0) ? g_q : g_k;
#pragma unroll
        for (int oo = 0; oo < 8; oo++)
            *(float4*)(dst + (size_t)(b*C + ty*8 + oo)*N + i0 + tx*4) =
                make_float4(acc[oo][0], acc[oo][1], acc[oo][2], acc[oo][3]);
    } else {
        // V goes out token-major: g_v[(b*N + i)*C + o]
        float* dst = g_v + (size_t)(b*N + i0 + tx*4)*C + ty*8;
#pragma unroll
        for (int ii = 0; ii < 4; ii++) {
            *(float4*)(dst + ii*C)     = make_float4(acc[0][ii], acc[1][ii], acc[2][ii], acc[3][ii]);
            *(float4*)(dst + ii*C + 4) = make_float4(acc[4][ii], acc[5][ii], acc[6][ii], acc[7][ii]);
        }
    }
}

// ---------------------------------------------------------------------------
// Kernel 2: flash attention.  grid (64 q-tiles, B), 256 threads.
// Bq = Bk = 64.  thread (ty,tx): S micro-tile 4q x 4k; O micro-tile 4q x 8c.
// ---------------------------------------------------------------------------
__global__ __launch_bounds__(TPB) void attn_kernel() {
    extern __shared__ float sm[];
    float* Qs = sm;              // [c][q]  128*64
    float* Ks = sm + 8192;       // [c][j]  128*64
    float* Vs = sm + 16384;      // [j][c]  64*128
    float* Ps = sm + 24576;      // [q][j]  64*64
    int b = blockIdx.y, q0 = blockIdx.x * 64;
    int tid = threadIdx.x, tx = tid & 15, ty = tid >> 4;

#pragma unroll
    for (int r = 0; r < 8; r++) {
        int idx4 = tid + TPB*r;
        int c = idx4 >> 4, j4 = idx4 & 15;
        ((float4*)Qs)[idx4] = *(const float4*)(g_q + (size_t)(b*C + c)*N + q0 + j4*4);
    }

    float m[4], l[4], O[4][8];
#pragma unroll
    for (int qq = 0; qq < 4; qq++) {
        m[qq] = -INFINITY; l[qq] = 0.f;
#pragma unroll
        for (int cc = 0; cc < 8; cc++) O[qq][cc] = 0.f;
    }

    for (int k0 = 0; k0 < N; k0 += 64) {
        __syncthreads();
#pragma unroll
        for (int r = 0; r < 8; r++) {
            int idx4 = tid + TPB*r;
            int c = idx4 >> 4, j4 = idx4 & 15;
            ((float4*)Ks)[idx4] = *(const float4*)(g_k + (size_t)(b*C + c)*N + k0 + j4*4);
        }
#pragma unroll
        for (int r = 0; r < 8; r++) {
            int idx4 = tid + TPB*r;
            int j = idx4 >> 5, c4 = idx4 & 31;
            ((float4*)Vs)[idx4] = *(const float4*)(g_v + (size_t)(b*N + k0 + j)*C + c4*4);
        }
        __syncthreads();

        // S = Q^T K  (4q x 4k per thread)
        float s[4][4];
#pragma unroll
        for (int qq = 0; qq < 4; qq++)
#pragma unroll
            for (int jj = 0; jj < 4; jj++) s[qq][jj] = 0.f;
#pragma unroll 8
        for (int c = 0; c < C; c++) {
            float4 qv = *(float4*)&Qs[c*64 + ty*4];
            float4 kv = *(float4*)&Ks[c*64 + tx*4];
            float qr[4] = {qv.x, qv.y, qv.z, qv.w};
            float kr[4] = {kv.x, kv.y, kv.z, kv.w};
#pragma unroll
            for (int qq = 0; qq < 4; qq++)
#pragma unroll
                for (int jj = 0; jj < 4; jj++) s[qq][jj] += qr[qq] * kr[jj];
        }

        // online softmax (row reduce across the 16 tx lanes)
#pragma unroll
        for (int qq = 0; qq < 4; qq++) {
            float tm = fmaxf(fmaxf(s[qq][0], s[qq][1]), fmaxf(s[qq][2], s[qq][3]));
#pragma unroll
            for (int off = 8; off; off >>= 1)
                tm = fmaxf(tm, __shfl_xor_sync(0xffffffffu, tm, off));
            float mn = fmaxf(m[qq], tm);
            float al = __expf(m[qq] - mn);
            float rs = 0.f;
#pragma unroll
            for (int jj = 0; jj < 4; jj++) {
                float p = __expf(s[qq][jj] - mn);
                s[qq][jj] = p; rs += p;
            }
#pragma unroll
            for (int off = 8; off; off >>= 1)
                rs += __shfl_xor_sync(0xffffffffu, rs, off);
            l[qq] = l[qq] * al + rs;
            m[qq] = mn;
#pragma unroll
            for (int cc = 0; cc < 8; cc++) O[qq][cc] *= al;
            *(float4*)&Ps[(ty*4 + qq)*64 + tx*4] =
                make_float4(s[qq][0], s[qq][1], s[qq][2], s[qq][3]);
        }
        __syncthreads();

        // O += P @ V   (per j: broadcast P, vectorized V)
#pragma unroll 4
        for (int j = 0; j < 64; j++) {
            float4 v0 = *(float4*)&Vs[j*C + tx*8];
            float4 v1 = *(float4*)&Vs[j*C + tx*8 + 4];
            float vr[8] = {v0.x, v0.y, v0.z, v0.w, v1.x, v1.y, v1.z, v1.w};
#pragma unroll
            for (int qq = 0; qq < 4; qq++) {
                float p = Ps[(ty*4 + qq)*64 + j];
#pragma unroll
                for (int cc = 0; cc < 8; cc++) O[qq][cc] += p * vr[cc];
            }
        }
    }

    // epilogue: normalize and write channel-major for the output conv
#pragma unroll
    for (int qq = 0; qq < 4; qq++) {
        float inv = 1.f / l[qq];
        int q = q0 + ty*4 + qq;
#pragma unroll
        for (int cc = 0; cc < 8; cc++)
            g_a[(size_t)(b*C + tx*8 + cc)*N + q] = O[qq][cc] * inv;
    }
}

// ---------------------------------------------------------------------------
// Kernel 3: output conv + bias + residual
// ---------------------------------------------------------------------------
__global__ __launch_bounds__(TPB) void out_kernel(const float* __restrict__ x,
        const float* __restrict__ bo, float* __restrict__ out) {
    extern __shared__ float sm[];
    float* Wt = sm;          // Wo transposed [c][o]
    float* Xs = sm + C*C;    // attn-out tile [c][i]
    int b = blockIdx.y, i0 = blockIdx.x * 64;
    int tid = threadIdx.x;

    const float4* wsrc = (const float4*)(g_wt + 3*C*C);
#pragma unroll
    for (int r = 0; r < 16; r++) ((float4*)Wt)[tid + TPB*r] = wsrc[tid + TPB*r];
#pragma unroll
    for (int r = 0; r < 8; r++) {
        int idx4 = tid + TPB*r;
        int c = idx4 >> 4, j4 = idx4 & 15;
        ((float4*)Xs)[idx4] = *(const float4*)(g_a + (size_t)(b*C + c)*N + i0 + j4*4);
    }
    __syncthreads();

    int tx = tid & 15, ty = tid >> 4;
    float acc[8][4];
#pragma unroll
    for (int oo = 0; oo < 8; oo++) {
        float bb = bo[ty*8 + oo];
#pragma unroll
        for (int ii = 0; ii < 4; ii++) acc[oo][ii] = bb;
    }
#pragma unroll 8
    for (int c = 0; c < C; c++) {
        float4 wa = *(float4*)&Wt[c*C + ty*8];
        float4 wb = *(float4*)&Wt[c*C + ty*8 + 4];
        float4 xv = *(float4*)&Xs[c*64 + tx*4];
        float w[8] = {wa.x, wa.y, wa.z, wa.w, wb.x, wb.y, wb.z, wb.w};
        float xr[4] = {xv.x, xv.y, xv.z, xv.w};
#pragma unroll
        for (int oo = 0; oo < 8; oo++)
#pragma unroll
            for (int ii = 0; ii < 4; ii++) acc[oo][ii] += w[oo] * xr[ii];
    }
#pragma unroll
    for (int oo = 0; oo < 8; oo++) {
        size_t base = (size_t)(b*C + ty*8 + oo)*N + i0 + tx*4;
        float4 xv = *(const float4*)(x + base);
        *(float4*)(out + base) =
            make_float4(acc[oo][0] + xv.x, acc[oo][1] + xv.y,
                        acc[oo][2] + xv.z, acc[oo][3] + xv.w);
    }
}

// ---------------------------------------------------------------------------
extern "C" void kernel_launch(void* const* d_in, const int* in_sizes, int n_in,
                              void* d_out, int out_size) {
    const float* x  = (const float*)d_in[0];
    const float* Wq = (const float*)d_in[1];
    const float* bq = (const float*)d_in[2];
    const float* Wk = (const float*)d_in[3];
    const float* bk = (const float*)d_in[4];
    const float* Wv = (const float*)d_in[5];
    const float* bv = (const float*)d_in[6];
    const float* Wo = (const float*)d_in[7];
    const float* bo = (const float*)d_in[8];
    float* out = (float*)d_out;

    const int SMEM_GEMM = (C*C + C*64) * sizeof(float);   // 96 KB
    const int SMEM_ATTN = (2*C*64 + 64*C + 64*64) * sizeof(float); // 112 KB
    cudaFuncSetAttribute(qkv_kernel,  cudaFuncAttributeMaxDynamicSharedMemorySize, SMEM_GEMM);
    cudaFuncSetAttribute(attn_kernel, cudaFuncAttributeMaxDynamicSharedMemorySize, SMEM_ATTN);
    cudaFuncSetAttribute(out_kernel,  cudaFuncAttributeMaxDynamicSharedMemorySize, SMEM_GEMM);

    wt_kernel<<<4, 256>>>(Wq, Wk, Wv, Wo);
    qkv_kernel<<<dim3(N/64, 3, B), TPB, SMEM_GEMM>>>(x, bq, bk, bv);
    attn_kernel<<<dim3(N/64, B), TPB, SMEM_ATTN>>>();
    out_kernel<<<dim3(N/64, B), TPB, SMEM_GEMM>>>(x, bo, out);
}

// round 2
// speedup vs baseline: 3.0708x; 3.0708x over previous
#include <cuda_runtime.h>
#include <cuda_bf16.h>
#include <math.h>
#include <stdint.h>

#define B 4
#define C 128
#define N 4096
#define TPB 256

// ---------------------------------------------------------------------------
// Scratch (device globals)
// ---------------------------------------------------------------------------
__device__ __align__(16) __nv_bfloat16 g_qh[B*N*C];  // token-major (b,n,c) hi
__device__ __align__(16) __nv_bfloat16 g_ql[B*N*C];  // token-major lo
__device__ __align__(16) __nv_bfloat16 g_kh[B*N*C];  // token-major hi
__device__ __align__(16) __nv_bfloat16 g_kl[B*N*C];  // token-major lo
__device__ __align__(16) __nv_bfloat16 g_vh[B*C*N];  // channel-major (b,c,n) hi
__device__ __align__(16) __nv_bfloat16 g_vl[B*C*N];  // channel-major lo
__device__ float g_a[B*C*N];                          // attn out, (b,c,n) fp32
__device__ float g_wt[4*C*C];                         // transposed weights [which][c][o]

// ---------------------------------------------------------------------------
// helpers
// ---------------------------------------------------------------------------
__device__ __forceinline__ uint32_t s2u(const void* p) {
    return (uint32_t)__cvta_generic_to_shared(p);
}
__device__ __forceinline__ void ldsm4(uint32_t r[4], uint32_t addr) {
    asm volatile("ldmatrix.sync.aligned.m8n8.x4.shared.b16 {%0,%1,%2,%3}, [%4];"
                 : "=r"(r[0]), "=r"(r[1]), "=r"(r[2]), "=r"(r[3]) : "r"(addr));
}
__device__ __forceinline__ void mma16816(float d[4], const uint32_t a[4],
                                         uint32_t b0, uint32_t b1) {
    asm("mma.sync.aligned.m16n8k16.row.col.f32.bf16.bf16.f32 "
        "{%0,%1,%2,%3}, {%4,%5,%6,%7}, {%8,%9}, {%0,%1,%2,%3};"
        : "+f"(d[0]), "+f"(d[1]), "+f"(d[2]), "+f"(d[3])
        : "r"(a[0]), "r"(a[1]), "r"(a[2]), "r"(a[3]), "r"(b0), "r"(b1));
}
__device__ __forceinline__ void split1(float x, __nv_bfloat16& h, __nv_bfloat16& l) {
    h = __float2bfloat16(x);
    l = __float2bfloat16(x - __bfloat162float(h));
}
__device__ __forceinline__ void pack2(float x, float y, uint32_t& h, uint32_t& l) {
    __nv_bfloat16 hx, lx, hy, ly;
    split1(x, hx, lx); split1(y, hy, ly);
    h = (uint32_t)__bfloat16_as_ushort(hx) | ((uint32_t)__bfloat16_as_ushort(hy) << 16);
    l = (uint32_t)__bfloat16_as_ushort(lx) | ((uint32_t)__bfloat16_as_ushort(ly) << 16);
}

// ---------------------------------------------------------------------------
// Kernel 0: transpose weights to [c][o]
// ---------------------------------------------------------------------------
__global__ void wt_kernel(const float* __restrict__ Wq, const float* __restrict__ Wk,
                          const float* __restrict__ Wv, const float* __restrict__ Wo) {
    int w = blockIdx.x;
    const float* src = (w == 0) ? Wq : (w == 1) ? Wk : (w == 2) ? Wv : Wo;
    for (int idx = threadIdx.x; idx < C*C; idx += blockDim.x) {
        int o = idx >> 7, c = idx & 127;
        g_wt[w*C*C + c*C + o] = src[idx];
    }
}

// ---------------------------------------------------------------------------
// Kernel 1: QKV 1x1 conv (fp32 SIMT), outputs bf16 hi/lo in mma-friendly layouts
// ---------------------------------------------------------------------------
__global__ __launch_bounds__(TPB) void qkv_kernel(const float* __restrict__ x,
        const float* __restrict__ bq, const float* __restrict__ bk,
        const float* __restrict__ bv) {
    extern __shared__ float sm[];
    float* Wt = sm;          // C*C
    float* Xs = sm + C*C;    // C*64
    int mode = blockIdx.y, b = blockIdx.z, i0 = blockIdx.x * 64;
    int tid = threadIdx.x;

    const float4* wsrc = (const float4*)(g_wt + mode*C*C);
#pragma unroll
    for (int r = 0; r < 16; r++) ((float4*)Wt)[tid + TPB*r] = wsrc[tid + TPB*r];
#pragma unroll
    for (int r = 0; r < 8; r++) {
        int idx4 = tid + TPB*r;
        int c = idx4 >> 4, j4 = idx4 & 15;
        ((float4*)Xs)[idx4] = *(const float4*)(x + (size_t)(b*C + c)*N + i0 + j4*4);
    }
    __syncthreads();

    int tx = tid & 15, ty = tid >> 4;
    const float* bias = (mode == 0) ? bq : (mode == 1) ? bk : bv;
    float acc[8][4];
#pragma unroll
    for (int oo = 0; oo < 8; oo++) {
        float bb = bias[ty*8 + oo];
#pragma unroll
        for (int ii = 0; ii < 4; ii++) acc[oo][ii] = bb;
    }
#pragma unroll 8
    for (int c = 0; c < C; c++) {
        float4 wa = *(float4*)&Wt[c*C + ty*8];
        float4 wb = *(float4*)&Wt[c*C + ty*8 + 4];
        float4 xv = *(float4*)&Xs[c*64 + tx*4];
        float w[8] = {wa.x, wa.y, wa.z, wa.w, wb.x, wb.y, wb.z, wb.w};
        float xr[4] = {xv.x, xv.y, xv.z, xv.w};
#pragma unroll
        for (int oo = 0; oo < 8; oo++)
#pragma unroll
            for (int ii = 0; ii < 4; ii++) acc[oo][ii] += w[oo] * xr[ii];
    }

    if (mode < 2) {
        // Q / K token-major: [(b*N + i)*C + o], 8 contiguous o per thread
        __nv_bfloat16* dh = mode ? g_kh : g_qh;
        __nv_bfloat16* dl = mode ? g_kl : g_ql;
#pragma unroll
        for (int ii = 0; ii < 4; ii++) {
            int i = i0 + tx*4 + ii;
            __align__(16) __nv_bfloat16 hb[8], lb[8];
#pragma unroll
            for (int oo = 0; oo < 8; oo++) split1(acc[oo][ii], hb[oo], lb[oo]);
            size_t base = (size_t)(b*N + i)*C + ty*8;
            *(uint4*)(dh + base) = *(uint4*)hb;
            *(uint4*)(dl + base) = *(uint4*)lb;
        }
    } else {
        // V channel-major: [(b*C + o)*N + i], 4 contiguous i per thread
#pragma unroll
        for (int oo = 0; oo < 8; oo++) {
            __align__(8) __nv_bfloat16 hb[4], lb[4];
#pragma unroll
            for (int ii = 0; ii < 4; ii++) split1(acc[oo][ii], hb[ii], lb[ii]);
            size_t base = (size_t)(b*C + ty*8 + oo)*N + i0 + tx*4;
            *(uint2*)(g_vh + base) = *(uint2*)hb;
            *(uint2*)(g_vl + base) = *(uint2*)lb;
        }
    }
}

// ---------------------------------------------------------------------------
// Kernel 2: flash attention with bf16 split-precision mma.sync
// Block: 128 q-tile, 8 warps (16 q-rows each), iterate 64-wide k-tiles.
// ---------------------------------------------------------------------------
#define PADQ 136   // bf16 row stride for Q/K smem tiles (16B offset per row)
#define PADV 72    // bf16 row stride for V smem tile

__global__ __launch_bounds__(TPB) void attn_kernel() {
    extern __shared__ __align__(16) unsigned char smraw[];
    __nv_bfloat16* Qh = (__nv_bfloat16*)smraw;       // [128][PADQ]
    __nv_bfloat16* Ql = Qh + 128*PADQ;
    __nv_bfloat16* Kh = Ql + 128*PADQ;               // [64][PADQ]
    __nv_bfloat16* Kl = Kh + 64*PADQ;
    __nv_bfloat16* Vh = Kl + 64*PADQ;                // [128][PADV]  rows=c, cols=j
    __nv_bfloat16* Vl = Vh + 128*PADV;

    int b = blockIdx.y, q0 = blockIdx.x * 128;
    int tid = threadIdx.x, wid = tid >> 5, lane = tid & 31;
    int gid = lane >> 2, tig = lane & 3;
    int qw = wid * 16;

    // load Q tile (hi & lo): 128 rows x 128 c
#pragma unroll
    for (int r = 0; r < 8; r++) {
        int idx = tid + TPB*r;                // 2048 uint4 per array
        int row = idx >> 4, c16 = idx & 15;
        size_t gbase = (size_t)(b*N + q0 + row)*C;
        *(uint4*)(Qh + row*PADQ + c16*8) = ((const uint4*)(g_qh + gbase))[c16];
        *(uint4*)(Ql + row*PADQ + c16*8) = ((const uint4*)(g_ql + gbase))[c16];
    }

    float m0 = -INFINITY, m1 = -INFINITY, l0 = 0.f, l1 = 0.f;
    float O[16][4];
#pragma unroll
    for (int cn = 0; cn < 16; cn++)
#pragma unroll
        for (int e = 0; e < 4; e++) O[cn][e] = 0.f;

    uint32_t sQh = s2u(Qh), sQl = s2u(Ql), sKh = s2u(Kh), sKl = s2u(Kl);
    uint32_t sVh = s2u(Vh), sVl = s2u(Vl);

    // ldmatrix per-lane address components
    int rowA = qw + (lane & 15);
    int colA = (lane >> 4) << 3;
    uint32_t offA = (uint32_t)(rowA*PADQ + colA) * 2;
    int rowB = (lane & 7) + ((lane >> 4) << 3);   // +8 for quads 2,3
    int colB = ((lane >> 3) & 1) << 3;            // +8 for odd quads

    for (int k0 = 0; k0 < N; k0 += 64) {
        __syncthreads();
        // K tile: 64 rows(j) x 128 c
#pragma unroll
        for (int r = 0; r < 4; r++) {
            int idx = tid + TPB*r;            // 1024 uint4
            int row = idx >> 4, c16 = idx & 15;
            size_t gbase = (size_t)(b*N + k0 + row)*C;
            *(uint4*)(Kh + row*PADQ + c16*8) = ((const uint4*)(g_kh + gbase))[c16];
            *(uint4*)(Kl + row*PADQ + c16*8) = ((const uint4*)(g_kl + gbase))[c16];
        }
        // V tile: 128 rows(c) x 64 j
#pragma unroll
        for (int r = 0; r < 4; r++) {
            int idx = tid + TPB*r;            // 1024 uint4
            int row = idx >> 3, j8 = idx & 7;
            size_t gbase = (size_t)(b*C + row)*N + k0;
            *(uint4*)(Vh + row*PADV + j8*8) = ((const uint4*)(g_vh + gbase))[j8];
            *(uint4*)(Vl + row*PADV + j8*8) = ((const uint4*)(g_vl + gbase))[j8];
        }
        __syncthreads();

        // ---- S = Q^T K : per warp 16q x 64j, k=c=128 ----
        float S[8][4];
#pragma unroll
        for (int jn = 0; jn < 8; jn++)
#pragma unroll
            for (int e = 0; e < 4; e++) S[jn][e] = 0.f;

#pragma unroll
        for (int kk = 0; kk < 8; kk++) {
            uint32_t ah[4], al_[4];
            ldsm4(ah,  sQh + offA + kk*32);
            ldsm4(al_, sQl + offA + kk*32);
#pragma unroll
            for (int jn2 = 0; jn2 < 4; jn2++) {
                uint32_t bh[4], bl[4];
                uint32_t boff = (uint32_t)((jn2*16 + rowB)*PADQ + kk*16 + colB) * 2;
                ldsm4(bh, sKh + boff);
                ldsm4(bl, sKl + boff);
                mma16816(S[2*jn2],   ah,  bh[0], bh[1]);
                mma16816(S[2*jn2],   ah,  bl[0], bl[1]);
                mma16816(S[2*jn2],   al_, bh[0], bh[1]);
                mma16816(S[2*jn2+1], ah,  bh[2], bh[3]);
                mma16816(S[2*jn2+1], ah,  bl[2], bl[3]);
                mma16816(S[2*jn2+1], al_, bh[2], bh[3]);
            }
        }

        // ---- online softmax (warp-local rows gid, gid+8) ----
        float mx0 = -INFINITY, mx1 = -INFINITY;
#pragma unroll
        for (int jn = 0; jn < 8; jn++) {
            mx0 = fmaxf(mx0, fmaxf(S[jn][0], S[jn][1]));
            mx1 = fmaxf(mx1, fmaxf(S[jn][2], S[jn][3]));
        }
        mx0 = fmaxf(mx0, __shfl_xor_sync(0xffffffffu, mx0, 1));
        mx0 = fmaxf(mx0, __shfl_xor_sync(0xffffffffu, mx0, 2));
        mx1 = fmaxf(mx1, __shfl_xor_sync(0xffffffffu, mx1, 1));
        mx1 = fmaxf(mx1, __shfl_xor_sync(0xffffffffu, mx1, 2));
        float nm0 = fmaxf(m0, mx0), nm1 = fmaxf(m1, mx1);
        float sc0 = __expf(m0 - nm0), sc1 = __expf(m1 - nm1);
        float sum0 = 0.f, sum1 = 0.f;
#pragma unroll
        for (int jn = 0; jn < 8; jn++) {
            S[jn][0] = __expf(S[jn][0] - nm0); sum0 += S[jn][0];
            S[jn][1] = __expf(S[jn][1] - nm0); sum0 += S[jn][1];
            S[jn][2] = __expf(S[jn][2] - nm1); sum1 += S[jn][2];
            S[jn][3] = __expf(S[jn][3] - nm1); sum1 += S[jn][3];
        }
        sum0 += __shfl_xor_sync(0xffffffffu, sum0, 1);
        sum0 += __shfl_xor_sync(0xffffffffu, sum0, 2);
        sum1 += __shfl_xor_sync(0xffffffffu, sum1, 1);
        sum1 += __shfl_xor_sync(0xffffffffu, sum1, 2);
        l0 = l0*sc0 + sum0; m0 = nm0;
        l1 = l1*sc1 + sum1; m1 = nm1;
#pragma unroll
        for (int cn = 0; cn < 16; cn++) {
            O[cn][0] *= sc0; O[cn][1] *= sc0;
            O[cn][2] *= sc1; O[cn][3] *= sc1;
        }

        // ---- O += P V : per warp 16q x 128c, k=j=64 ----
#pragma unroll
        for (int s = 0; s < 4; s++) {
            uint32_t ph[4], pl[4];
            pack2(S[2*s][0],   S[2*s][1],   ph[0], pl[0]);
            pack2(S[2*s][2],   S[2*s][3],   ph[1], pl[1]);
            pack2(S[2*s+1][0], S[2*s+1][1], ph[2], pl[2]);
            pack2(S[2*s+1][2], S[2*s+1][3], ph[3], pl[3]);
#pragma unroll
            for (int cn2 = 0; cn2 < 8; cn2++) {
                uint32_t vh[4], vl[4];
                uint32_t voff = (uint32_t)((cn2*16 + rowB)*PADV + s*16 + colB) * 2;
                ldsm4(vh, sVh + voff);
                ldsm4(vl, sVl + voff);
                mma16816(O[2*cn2],   ph, vh[0], vh[1]);
                mma16816(O[2*cn2],   ph, vl[0], vl[1]);
                mma16816(O[2*cn2],   pl, vh[0], vh[1]);
                mma16816(O[2*cn2+1], ph, vh[2], vh[3]);
                mma16816(O[2*cn2+1], ph, vl[2], vl[3]);
                mma16816(O[2*cn2+1], pl, vh[2], vh[3]);
            }
        }
    }

    // epilogue: normalize, write channel-major fp32
    float inv0 = 1.f / l0, inv1 = 1.f / l1;
    int qg0 = q0 + qw + gid, qg1 = qg0 + 8;
#pragma unroll
    for (int cn = 0; cn < 16; cn++) {
        int c = cn*8 + tig*2;
        size_t base = (size_t)(b*C + c)*N;
        g_a[base + qg0]     = O[cn][0] * inv0;
        g_a[base + N + qg0] = O[cn][1] * inv0;
        g_a[base + qg1]     = O[cn][2] * inv1;
        g_a[base + N + qg1] = O[cn][3] * inv1;
    }
}

// ---------------------------------------------------------------------------
// Kernel 3: output conv + bias + residual (fp32 SIMT)
// ---------------------------------------------------------------------------
__global__ __launch_bounds__(TPB) void out_kernel(const float* __restrict__ x,
        const float* __restrict__ bo, float* __restrict__ out) {
    extern __shared__ float sm[];
    float* Wt = sm;
    float* Xs = sm + C*C;
    int b = blockIdx.y, i0 = blockIdx.x * 64;
    int tid = threadIdx.x;

    const float4* wsrc = (const float4*)(g_wt + 3*C*C);
#pragma unroll
    for (int r = 0; r < 16; r++) ((float4*)Wt)[tid + TPB*r] = wsrc[tid + TPB*r];
#pragma unroll
    for (int r = 0; r < 8; r++) {
        int idx4 = tid + TPB*r;
        int c = idx4 >> 4, j4 = idx4 & 15;
        ((float4*)Xs)[idx4] = *(const float4*)(g_a + (size_t)(b*C + c)*N + i0 + j4*4);
    }
    __syncthreads();

    int tx = tid & 15, ty = tid >> 4;
    float acc[8][4];
#pragma unroll
    for (int oo = 0; oo < 8; oo++) {
        float bb = bo[ty*8 + oo];
#pragma unroll
        for (int ii = 0; ii < 4; ii++) acc[oo][ii] = bb;
    }
#pragma unroll 8
    for (int c = 0; c < C; c++) {
        float4 wa = *(float4*)&Wt[c*C + ty*8];
        float4 wb = *(float4*)&Wt[c*C + ty*8 + 4];
        float4 xv = *(float4*)&Xs[c*64 + tx*4];
        float w[8] = {wa.x, wa.y, wa.z, wa.w, wb.x, wb.y, wb.z, wb.w};
        float xr[4] = {xv.x, xv.y, xv.z, xv.w};
#pragma unroll
        for (int oo = 0; oo < 8; oo++)
#pragma unroll
            for (int ii = 0; ii < 4; ii++) acc[oo][ii] += w[oo] * xr[ii];
    }
#pragma unroll
    for (int oo = 0; oo < 8; oo++) {
        size_t base = (size_t)(b*C + ty*8 + oo)*N + i0 + tx*4;
        float4 xv = *(const float4*)(x + base);
        *(float4*)(out + base) =
            make_float4(acc[oo][0] + xv.x, acc[oo][1] + xv.y,
                        acc[oo][2] + xv.z, acc[oo][3] + xv.w);
    }
}

// ---------------------------------------------------------------------------
extern "C" void kernel_launch(void* const* d_in, const int* in_sizes, int n_in,
                              void* d_out, int out_size) {
    const float* x  = (const float*)d_in[0];
    const float* Wq = (const float*)d_in[1];
    const float* bq = (const float*)d_in[2];
    const float* Wk = (const float*)d_in[3];
    const float* bk = (const float*)d_in[4];
    const float* Wv = (const float*)d_in[5];
    const float* bv = (const float*)d_in[6];
    const float* Wo = (const float*)d_in[7];
    const float* bo = (const float*)d_in[8];
    float* out = (float*)d_out;

    const int SMEM_GEMM = (C*C + C*64) * sizeof(float);                 // 96 KB
    const int SMEM_ATTN = (2*128*PADQ + 2*64*PADQ + 2*128*PADV) * 2;    // 141312 B
    cudaFuncSetAttribute(qkv_kernel,  cudaFuncAttributeMaxDynamicSharedMemorySize, SMEM_GEMM);
    cudaFuncSetAttribute(attn_kernel, cudaFuncAttributeMaxDynamicSharedMemorySize, SMEM_ATTN);
    cudaFuncSetAttribute(out_kernel,  cudaFuncAttributeMaxDynamicSharedMemorySize, SMEM_GEMM);

    wt_kernel<<<4, 256>>>(Wq, Wk, Wv, Wo);
    qkv_kernel<<<dim3(N/64, 3, B), TPB, SMEM_GEMM>>>(x, bq, bk, bv);
    attn_kernel<<<dim3(N/128, B), TPB, SMEM_ATTN>>>();
    out_kernel<<<dim3(N/64, B), TPB, SMEM_GEMM>>>(x, bo, out);
}

// round 3
// speedup vs baseline: 3.3373x; 1.0868x over previous
#include <cuda_runtime.h>
#include <cuda_bf16.h>
#include <math.h>
#include <stdint.h>

#define B 4
#define C 128
#define N 4096
#define TPB 256

// ---------------------------------------------------------------------------
// Scratch (device globals)
// ---------------------------------------------------------------------------
__device__ __align__(16) __nv_bfloat16 g_qh[B*N*C];  // token-major (b,n,c) hi
__device__ __align__(16) __nv_bfloat16 g_ql[B*N*C];  // token-major lo
__device__ __align__(16) __nv_bfloat16 g_kh[B*N*C];  // token-major hi
__device__ __align__(16) __nv_bfloat16 g_kl[B*N*C];  // token-major lo
__device__ __align__(16) __nv_bfloat16 g_vh[B*C*N];  // channel-major (b,c,n) hi
__device__ __align__(16) __nv_bfloat16 g_vl[B*C*N];  // channel-major lo
__device__ float g_a[B*C*N];                          // attn out, (b,c,n) fp32
__device__ float g_wt[4*C*C];                         // transposed weights [which][c][o]

// ---------------------------------------------------------------------------
// helpers
// ---------------------------------------------------------------------------
__device__ __forceinline__ uint32_t s2u(const void* p) {
    return (uint32_t)__cvta_generic_to_shared(p);
}
__device__ __forceinline__ void ldsm4(uint32_t r[4], uint32_t addr) {
    asm volatile("ldmatrix.sync.aligned.m8n8.x4.shared.b16 {%0,%1,%2,%3}, [%4];"
                 : "=r"(r[0]), "=r"(r[1]), "=r"(r[2]), "=r"(r[3]) : "r"(addr));
}
__device__ __forceinline__ void mma16816(float d[4], const uint32_t a[4],
                                         uint32_t b0, uint32_t b1) {
    asm("mma.sync.aligned.m16n8k16.row.col.f32.bf16.bf16.f32 "
        "{%0,%1,%2,%3}, {%4,%5,%6,%7}, {%8,%9}, {%0,%1,%2,%3};"
        : "+f"(d[0]), "+f"(d[1]), "+f"(d[2]), "+f"(d[3])
        : "r"(a[0]), "r"(a[1]), "r"(a[2]), "r"(a[3]), "r"(b0), "r"(b1));
}
__device__ __forceinline__ void split1(float x, __nv_bfloat16& h, __nv_bfloat16& l) {
    h = __float2bfloat16(x);
    l = __float2bfloat16(x - __bfloat162float(h));
}
__device__ __forceinline__ void pack2(float x, float y, uint32_t& h, uint32_t& l) {
    __nv_bfloat16 hx, lx, hy, ly;
    split1(x, hx, lx); split1(y, hy, ly);
    h = (uint32_t)__bfloat16_as_ushort(hx) | ((uint32_t)__bfloat16_as_ushort(hy) << 16);
    l = (uint32_t)__bfloat16_as_ushort(lx) | ((uint32_t)__bfloat16_as_ushort(ly) << 16);
}
__device__ __forceinline__ void cpa16(uint32_t d, const void* s) {
    asm volatile("cp.async.cg.shared.global [%0], [%1], 16;" :: "r"(d), "l"(s));
}
#define CP_COMMIT() asm volatile("cp.async.commit_group;" ::)
#define CP_WAIT(n)  asm volatile("cp.async.wait_group %0;" :: "n"(n))

// ---------------------------------------------------------------------------
// Kernel 0: transpose weights to [c][o]
// ---------------------------------------------------------------------------
__global__ void wt_kernel(const float* __restrict__ Wq, const float* __restrict__ Wk,
                          const float* __restrict__ Wv, const float* __restrict__ Wo) {
    int w = blockIdx.x;
    const float* src = (w == 0) ? Wq : (w == 1) ? Wk : (w == 2) ? Wv : Wo;
    for (int idx = threadIdx.x; idx < C*C; idx += blockDim.x) {
        int o = idx >> 7, c = idx & 127;
        g_wt[w*C*C + c*C + o] = src[idx];
    }
}

// ---------------------------------------------------------------------------
// Kernel 1: QKV 1x1 conv (fp32 SIMT), outputs bf16 hi/lo in mma-friendly layouts
// ---------------------------------------------------------------------------
__global__ __launch_bounds__(TPB) void qkv_kernel(const float* __restrict__ x,
        const float* __restrict__ bq, const float* __restrict__ bk,
        const float* __restrict__ bv) {
    extern __shared__ float sm[];
    float* Wt = sm;          // C*C
    float* Xs = sm + C*C;    // C*64
    int mode = blockIdx.y, b = blockIdx.z, i0 = blockIdx.x * 64;
    int tid = threadIdx.x;

    const float4* wsrc = (const float4*)(g_wt + mode*C*C);
#pragma unroll
    for (int r = 0; r < 16; r++) ((float4*)Wt)[tid + TPB*r] = wsrc[tid + TPB*r];
#pragma unroll
    for (int r = 0; r < 8; r++) {
        int idx4 = tid + TPB*r;
        int c = idx4 >> 4, j4 = idx4 & 15;
        ((float4*)Xs)[idx4] = *(const float4*)(x + (size_t)(b*C + c)*N + i0 + j4*4);
    }
    __syncthreads();

    int tx = tid & 15, ty = tid >> 4;
    const float* bias = (mode == 0) ? bq : (mode == 1) ? bk : bv;
    float acc[8][4];
#pragma unroll
    for (int oo = 0; oo < 8; oo++) {
        float bb = bias[ty*8 + oo];
#pragma unroll
        for (int ii = 0; ii < 4; ii++) acc[oo][ii] = bb;
    }
#pragma unroll 8
    for (int c = 0; c < C; c++) {
        float4 wa = *(float4*)&Wt[c*C + ty*8];
        float4 wb = *(float4*)&Wt[c*C + ty*8 + 4];
        float4 xv = *(float4*)&Xs[c*64 + tx*4];
        float w[8] = {wa.x, wa.y, wa.z, wa.w, wb.x, wb.y, wb.z, wb.w};
        float xr[4] = {xv.x, xv.y, xv.z, xv.w};
#pragma unroll
        for (int oo = 0; oo < 8; oo++)
#pragma unroll
            for (int ii = 0; ii < 4; ii++) acc[oo][ii] += w[oo] * xr[ii];
    }

    if (mode < 2) {
        __nv_bfloat16* dh = mode ? g_kh : g_qh;
        __nv_bfloat16* dl = mode ? g_kl : g_ql;
#pragma unroll
        for (int ii = 0; ii < 4; ii++) {
            int i = i0 + tx*4 + ii;
            __align__(16) __nv_bfloat16 hb[8], lb[8];
#pragma unroll
            for (int oo = 0; oo < 8; oo++) split1(acc[oo][ii], hb[oo], lb[oo]);
            size_t base = (size_t)(b*N + i)*C + ty*8;
            *(uint4*)(dh + base) = *(uint4*)hb;
            *(uint4*)(dl + base) = *(uint4*)lb;
        }
    } else {
#pragma unroll
        for (int oo = 0; oo < 8; oo++) {
            __align__(8) __nv_bfloat16 hb[4], lb[4];
#pragma unroll
            for (int ii = 0; ii < 4; ii++) split1(acc[oo][ii], hb[ii], lb[ii]);
            size_t base = (size_t)(b*C + ty*8 + oo)*N + i0 + tx*4;
            *(uint2*)(g_vh + base) = *(uint2*)hb;
            *(uint2*)(g_vl + base) = *(uint2*)lb;
        }
    }
}

// ---------------------------------------------------------------------------
// Kernel 2: flash attention, bf16 split mma.sync + cp.async double buffering
// ---------------------------------------------------------------------------
#define PADQ 136
#define PADV 72

__device__ __forceinline__ void load_kv(uint32_t kh, uint32_t kl, uint32_t vh,
                                        uint32_t vl, int b, int k0, int tid) {
#pragma unroll
    for (int r = 0; r < 4; r++) {
        int idx = tid + TPB*r;
        int row = idx >> 4, c16 = idx & 15;
        size_t g = (size_t)(b*N + k0 + row)*C + c16*8;
        uint32_t d = (uint32_t)(row*PADQ + c16*8) * 2;
        cpa16(kh + d, g_kh + g);
        cpa16(kl + d, g_kl + g);
    }
#pragma unroll
    for (int r = 0; r < 4; r++) {
        int idx = tid + TPB*r;
        int row = idx >> 3, j8 = idx & 7;
        size_t g = (size_t)(b*C + row)*N + k0 + j8*8;
        uint32_t d = (uint32_t)(row*PADV + j8*8) * 2;
        cpa16(vh + d, g_vh + g);
        cpa16(vl + d, g_vl + g);
    }
}

__global__ __launch_bounds__(TPB, 1) void attn_kernel() {
    extern __shared__ __align__(16) __nv_bfloat16 smb[];
    __nv_bfloat16* Qh = smb;                         // [128][PADQ]
    __nv_bfloat16* Ql = Qh + 128*PADQ;
    __nv_bfloat16* Kbase = Ql + 128*PADQ;            // 4 x [64][PADQ]  (hi0,lo0,hi1,lo1)
    __nv_bfloat16* Vbase = Kbase + 4*64*PADQ;        // 4 x [128][PADV] (hi0,lo0,hi1,lo1)

    int b = blockIdx.y, q0 = blockIdx.x * 128;
    int tid = threadIdx.x, wid = tid >> 5, lane = tid & 31;
    int gid = lane >> 2, tig = lane & 3;
    int qw = wid * 16;

    const uint32_t KBUF = 64*PADQ*2;     // bytes per K sub-tile
    const uint32_t VBUF = 128*PADV*2;    // bytes per V sub-tile
    uint32_t sQh = s2u(Qh), sQl = s2u(Ql);
    uint32_t sK0 = s2u(Kbase), sV0 = s2u(Vbase);

    // load Q tile (hi & lo)
#pragma unroll
    for (int r = 0; r < 8; r++) {
        int idx = tid + TPB*r;
        int row = idx >> 4, c16 = idx & 15;
        size_t gbase = (size_t)(b*N + q0 + row)*C;
        *(uint4*)(Qh + row*PADQ + c16*8) = ((const uint4*)(g_qh + gbase))[c16];
        *(uint4*)(Ql + row*PADQ + c16*8) = ((const uint4*)(g_ql + gbase))[c16];
    }
    __syncthreads();

    // ldmatrix per-lane address components
    int rowA = qw + (lane & 15);
    int colA = (lane >> 4) << 3;
    uint32_t offA = (uint32_t)(rowA*PADQ + colA) * 2;
    int rowB = (lane & 7) + ((lane >> 4) << 3);
    int colB = ((lane >> 3) & 1) << 3;

    // hoist Q-hi fragments (loop-invariant)
    uint32_t qh[8][4];
#pragma unroll
    for (int kk = 0; kk < 8; kk++) ldsm4(qh[kk], sQh + offA + kk*32);

    // prefetch first K/V tile
    load_kv(sK0, sK0 + KBUF, sV0, sV0 + VBUF, b, 0, tid);
    CP_COMMIT();

    float m0 = -INFINITY, m1 = -INFINITY, l0 = 0.f, l1 = 0.f;
    float O[16][4];
#pragma unroll
    for (int cn = 0; cn < 16; cn++)
#pragma unroll
        for (int e = 0; e < 4; e++) O[cn][e] = 0.f;

    const int NB = N/64;
    for (int it = 0; it < NB; it++) {
        int cur = it & 1;
        if (it + 1 < NB) {
            uint32_t nk = sK0 + (cur^1)*2*KBUF, nv = sV0 + (cur^1)*2*VBUF;
            load_kv(nk, nk + KBUF, nv, nv + VBUF, b, (it+1)*64, tid);
            CP_COMMIT();
            CP_WAIT(1);
        } else {
            CP_WAIT(0);
        }
        __syncthreads();

        uint32_t cKh = sK0 + cur*2*KBUF, cKl = cKh + KBUF;
        uint32_t cVh = sV0 + cur*2*VBUF, cVl = cVh + VBUF;

        // ---- S = Q^T K ----
        float S[8][4];
#pragma unroll
        for (int jn = 0; jn < 8; jn++)
#pragma unroll
            for (int e = 0; e < 4; e++) S[jn][e] = 0.f;

#pragma unroll
        for (int kk = 0; kk < 8; kk++) {
            uint32_t qlk[4];
            ldsm4(qlk, sQl + offA + kk*32);
#pragma unroll
            for (int jn2 = 0; jn2 < 4; jn2++) {
                uint32_t bh[4], bl[4];
                uint32_t boff = (uint32_t)((jn2*16 + rowB)*PADQ + kk*16 + colB) * 2;
                ldsm4(bh, cKh + boff);
                ldsm4(bl, cKl + boff);
                mma16816(S[2*jn2],   qh[kk], bh[0], bh[1]);
                mma16816(S[2*jn2],   qh[kk], bl[0], bl[1]);
                mma16816(S[2*jn2],   qlk,    bh[0], bh[1]);
                mma16816(S[2*jn2+1], qh[kk], bh[2], bh[3]);
                mma16816(S[2*jn2+1], qh[kk], bl[2], bl[3]);
                mma16816(S[2*jn2+1], qlk,    bh[2], bh[3]);
            }
        }

        // ---- online softmax ----
        float mx0 = -INFINITY, mx1 = -INFINITY;
#pragma unroll
        for (int jn = 0; jn < 8; jn++) {
            mx0 = fmaxf(mx0, fmaxf(S[jn][0], S[jn][1]));
            mx1 = fmaxf(mx1, fmaxf(S[jn][2], S[jn][3]));
        }
        mx0 = fmaxf(mx0, __shfl_xor_sync(0xffffffffu, mx0, 1));
        mx0 = fmaxf(mx0, __shfl_xor_sync(0xffffffffu, mx0, 2));
        mx1 = fmaxf(mx1, __shfl_xor_sync(0xffffffffu, mx1, 1));
        mx1 = fmaxf(mx1, __shfl_xor_sync(0xffffffffu, mx1, 2));
        float nm0 = fmaxf(m0, mx0), nm1 = fmaxf(m1, mx1);
        float sc0 = __expf(m0 - nm0), sc1 = __expf(m1 - nm1);
        float sum0 = 0.f, sum1 = 0.f;
#pragma unroll
        for (int jn = 0; jn < 8; jn++) {
            S[jn][0] = __expf(S[jn][0] - nm0); sum0 += S[jn][0];
            S[jn][1] = __expf(S[jn][1] - nm0); sum0 += S[jn][1];
            S[jn][2] = __expf(S[jn][2] - nm1); sum1 += S[jn][2];
            S[jn][3] = __expf(S[jn][3] - nm1); sum1 += S[jn][3];
        }
        sum0 += __shfl_xor_sync(0xffffffffu, sum0, 1);
        sum0 += __shfl_xor_sync(0xffffffffu, sum0, 2);
        sum1 += __shfl_xor_sync(0xffffffffu, sum1, 1);
        sum1 += __shfl_xor_sync(0xffffffffu, sum1, 2);
        l0 = l0*sc0 + sum0; m0 = nm0;
        l1 = l1*sc1 + sum1; m1 = nm1;
#pragma unroll
        for (int cn = 0; cn < 16; cn++) {
            O[cn][0] *= sc0; O[cn][1] *= sc0;
            O[cn][2] *= sc1; O[cn][3] *= sc1;
        }

        // ---- O += P V ----
#pragma unroll
        for (int s = 0; s < 4; s++) {
            uint32_t ph[4], pl[4];
            pack2(S[2*s][0],   S[2*s][1],   ph[0], pl[0]);
            pack2(S[2*s][2],   S[2*s][3],   ph[1], pl[1]);
            pack2(S[2*s+1][0], S[2*s+1][1], ph[2], pl[2]);
            pack2(S[2*s+1][2], S[2*s+1][3], ph[3], pl[3]);
#pragma unroll
            for (int cn2 = 0; cn2 < 8; cn2++) {
                uint32_t vh[4], vl[4];
                uint32_t voff = (uint32_t)((cn2*16 + rowB)*PADV + s*16 + colB) * 2;
                ldsm4(vh, cVh + voff);
                ldsm4(vl, cVl + voff);
                mma16816(O[2*cn2],   ph, vh[0], vh[1]);
                mma16816(O[2*cn2],   ph, vl[0], vl[1]);
                mma16816(O[2*cn2],   pl, vh[0], vh[1]);
                mma16816(O[2*cn2+1], ph, vh[2], vh[3]);
                mma16816(O[2*cn2+1], ph, vl[2], vl[3]);
                mma16816(O[2*cn2+1], pl, vh[2], vh[3]);
            }
        }
        __syncthreads();
    }

    // epilogue: normalize, write channel-major fp32
    float inv0 = 1.f / l0, inv1 = 1.f / l1;
    int qg0 = q0 + qw + gid, qg1 = qg0 + 8;
#pragma unroll
    for (int cn = 0; cn < 16; cn++) {
        int c = cn*8 + tig*2;
        size_t base = (size_t)(b*C + c)*N;
        g_a[base + qg0]     = O[cn][0] * inv0;
        g_a[base + N + qg0] = O[cn][1] * inv0;
        g_a[base + qg1]     = O[cn][2] * inv1;
        g_a[base + N + qg1] = O[cn][3] * inv1;
    }
}

// ---------------------------------------------------------------------------
// Kernel 3: output conv + bias + residual (fp32 SIMT)
// ---------------------------------------------------------------------------
__global__ __launch_bounds__(TPB) void out_kernel(const float* __restrict__ x,
        const float* __restrict__ bo, float* __restrict__ out) {
    extern __shared__ float sm[];
    float* Wt = sm;
    float* Xs = sm + C*C;
    int b = blockIdx.y, i0 = blockIdx.x * 64;
    int tid = threadIdx.x;

    const float4* wsrc = (const float4*)(g_wt + 3*C*C);
#pragma unroll
    for (int r = 0; r < 16; r++) ((float4*)Wt)[tid + TPB*r] = wsrc[tid + TPB*r];
#pragma unroll
    for (int r = 0; r < 8; r++) {
        int idx4 = tid + TPB*r;
        int c = idx4 >> 4, j4 = idx4 & 15;
        ((float4*)Xs)[idx4] = *(const float4*)(g_a + (size_t)(b*C + c)*N + i0 + j4*4);
    }
    __syncthreads();

    int tx = tid & 15, ty = tid >> 4;
    float acc[8][4];
#pragma unroll
    for (int oo = 0; oo < 8; oo++) {
        float bb = bo[ty*8 + oo];
#pragma unroll
        for (int ii = 0; ii < 4; ii++) acc[oo][ii] = bb;
    }
#pragma unroll 8
    for (int c = 0; c < C; c++) {
        float4 wa = *(float4*)&Wt[c*C + ty*8];
        float4 wb = *(float4*)&Wt[c*C + ty*8 + 4];
        float4 xv = *(float4*)&Xs[c*64 + tx*4];
        float w[8] = {wa.x, wa.y, wa.z, wa.w, wb.x, wb.y, wb.z, wb.w};
        float xr[4] = {xv.x, xv.y, xv.z, xv.w};
#pragma unroll
        for (int oo = 0; oo < 8; oo++)
#pragma unroll
            for (int ii = 0; ii < 4; ii++) acc[oo][ii] += w[oo] * xr[ii];
    }
#pragma unroll
    for (int oo = 0; oo < 8; oo++) {
        size_t base = (size_t)(b*C + ty*8 + oo)*N + i0 + tx*4;
        float4 xv = *(const float4*)(x + base);
        *(float4*)(out + base) =
            make_float4(acc[oo][0] + xv.x, acc[oo][1] + xv.y,
                        acc[oo][2] + xv.z, acc[oo][3] + xv.w);
    }
}

// ---------------------------------------------------------------------------
extern "C" void kernel_launch(void* const* d_in, const int* in_sizes, int n_in,
                              void* d_out, int out_size) {
    const float* x  = (const float*)d_in[0];
    const float* Wq = (const float*)d_in[1];
    const float* bq = (const float*)d_in[2];
    const float* Wk = (const float*)d_in[3];
    const float* bk = (const float*)d_in[4];
    const float* Wv = (const float*)d_in[5];
    const float* bv = (const float*)d_in[6];
    const float* Wo = (const float*)d_in[7];
    const float* bo = (const float*)d_in[8];
    float* out = (float*)d_out;

    const int SMEM_GEMM = (C*C + C*64) * sizeof(float);  // 96 KB
    const int SMEM_ATTN = (2*128*PADQ + 4*64*PADQ + 4*128*PADV) * 2;  // 212992 B
    cudaFuncSetAttribute(qkv_kernel,  cudaFuncAttributeMaxDynamicSharedMemorySize, SMEM_GEMM);
    cudaFuncSetAttribute(attn_kernel, cudaFuncAttributeMaxDynamicSharedMemorySize, SMEM_ATTN);
    cudaFuncSetAttribute(out_kernel,  cudaFuncAttributeMaxDynamicSharedMemorySize, SMEM_GEMM);

    wt_kernel<<<4, 256>>>(Wq, Wk, Wv, Wo);
    qkv_kernel<<<dim3(N/64, 3, B), TPB, SMEM_GEMM>>>(x, bq, bk, bv);
    attn_kernel<<<dim3(N/128, B), TPB, SMEM_ATTN>>>();
    out_kernel<<<dim3(N/64, B), TPB, SMEM_GEMM>>>(x, bo, out);
}